// round 1
// baseline (speedup 1.0000x reference)
#include <cuda_runtime.h>
#include <cuda_bf16.h>

// PointMatcher: pred (N=1024,20,2) vs gt (M=2048,20,2)
// dist(i,j) = mean_p ||pred[i,p]-gt[j,p]||_2 ; argmin over j per i.
// Outputs concatenated into d_out (float32):
//   [0 .. N*40)            matched_points = gt[argmin]
//   [N*40 .. N*41)         confidence = (min>2) ? 0 : exp(-min)
//   [N*41 .. N*42)         matched_indices (as float)

#define BI 4          // pred rows per block
#define TJ 128        // gt rows per shared tile
#define HJ 64         // j-lanes (each thread handles 2 gt rows per tile)
#define P  20
#define ROWF 40       // floats per gt/pred row
#define ROWP 42       // padded shared row stride (kills bank conflicts: 42 mod 32 = 10)
#define THREADS 256

__device__ __forceinline__ float fsqrt_approx(float x) {
    float r;
    asm("sqrt.approx.f32 %0, %1;" : "=f"(r) : "f"(x));
    return r;
}

__global__ __launch_bounds__(THREADS)
void pointmatcher_kernel(const float* __restrict__ pred,
                         const float* __restrict__ gt,
                         float* __restrict__ out_mp,
                         float* __restrict__ out_conf,
                         float* __restrict__ out_idx,
                         int N, int M)
{
    __shared__ float tile[TJ * ROWP];
    __shared__ unsigned long long best[BI];

    const int tid   = threadIdx.x;
    const int il    = tid & (BI - 1);   // pred row within block
    const int jlane = tid >> 2;         // 0..63
    const int i     = blockIdx.x * BI + il;

    if (tid < BI) best[tid] = ~0ull;    // covered by first __syncthreads below

    // Load this thread's pred row into registers (as float2 per point)
    float2 pr[P];
    {
        const float2* p2 = (const float2*)(pred + i * ROWF);
        #pragma unroll
        for (int p = 0; p < P; p++) pr[p] = p2[p];
    }

    float minv = 3.402823466e+38f;  // min of SUM (mean deferred)
    int   minj = 0;

    for (int jt = 0; jt < M; jt += TJ) {
        __syncthreads();  // previous tile fully consumed / best[] init visible
        // Coalesced tile load: 5120 floats, 20 per thread
        for (int idx = tid; idx < TJ * ROWF; idx += THREADS) {
            int jj = idx / ROWF;
            int k  = idx - jj * ROWF;
            tile[jj * ROWP + k] = gt[jt * ROWF + idx];
        }
        __syncthreads();

        const float2* t0 = (const float2*)(tile + jlane * ROWP);
        const float2* t1 = (const float2*)(tile + (jlane + HJ) * ROWP);
        float sum0 = 0.f, sum1 = 0.f;
        #pragma unroll
        for (int p = 0; p < P; p++) {
            float2 g0 = t0[p];
            float2 g1 = t1[p];
            float dx0 = pr[p].x - g0.x, dy0 = pr[p].y - g0.y;
            float dx1 = pr[p].x - g1.x, dy1 = pr[p].y - g1.y;
            sum0 += fsqrt_approx(fmaf(dx0, dx0, dy0 * dy0));
            sum1 += fsqrt_approx(fmaf(dx1, dx1, dy1 * dy1));
        }
        int j0 = jt + jlane;
        int j1 = jt + jlane + HJ;
        if (sum0 < minv) { minv = sum0; minj = j0; }  // j ascending per thread:
        if (sum1 < minv) { minv = sum1; minj = j1; }  // strict '<' keeps first tie
    }

    // Block-level argmin reduction: packed (dist_bits, j); positive-float bits
    // are monotone, so min key = (min dist, then min j) == argmin semantics.
    unsigned long long key =
        ((unsigned long long)__float_as_uint(minv) << 32) | (unsigned int)minj;
    atomicMin(&best[il], key);
    __syncthreads();

    // Finalize scalar outputs (one thread per pred row)
    if (tid < BI) {
        unsigned long long b = best[tid];
        int j = (int)(unsigned int)b;
        float sumv = __uint_as_float((unsigned int)(b >> 32));
        float md   = sumv * (1.0f / (float)P);
        int row    = blockIdx.x * BI + tid;
        out_conf[row] = (md > 2.0f) ? 0.0f : expf(-md);
        out_idx[row]  = (float)j;
    }
    // Gather matched gt rows (40 floats x BI rows, 160 threads participate)
    if (tid < BI * ROWF) {
        int ilg = tid / ROWF;
        int k   = tid - ilg * ROWF;
        int j   = (int)(unsigned int)best[ilg];
        out_mp[(blockIdx.x * BI + ilg) * ROWF + k] = gt[j * ROWF + k];
    }
}

extern "C" void kernel_launch(void* const* d_in, const int* in_sizes, int n_in,
                              void* d_out, int out_size)
{
    const float* pred = (const float*)d_in[0];
    const float* gt   = (const float*)d_in[1];
    float* out        = (float*)d_out;

    int N = in_sizes[0] / ROWF;   // 1024
    int M = in_sizes[1] / ROWF;   // 2048

    float* out_mp   = out;
    float* out_conf = out + (size_t)N * ROWF;
    float* out_idx  = out + (size_t)N * ROWF + N;

    pointmatcher_kernel<<<N / BI, THREADS>>>(pred, gt, out_mp, out_conf, out_idx, N, M);
}